// round 6
// baseline (speedup 1.0000x reference)
#include <cuda_runtime.h>

#define THREADS 256
#define C16 16
#define DIM 96
#define HW (DIM*DIM)
#define DHW (DIM*DIM*DIM)
#define FEATS 512
#define KTOT 1024
#define KPB 512            // k per block (KSPLIT=2)
#define NB 8               // fixed brick edge
// padded strides (float2 units): x=1, y=9, z=77
// bank(4B) = (2*(13*jz + 9*jy + jx)) mod 32 -> no collisions for |delta|<=1 in any axis
#define SY 9
#define SZ 77
#define PSV (NB*SZ)        // 616 float2 per channel-pair slab
#define NPAIR 8            // 16 channels = 8 float2 pairs
#define BRICK_E (NPAIR*PSV) // 4928 float2 = 38.5KB

__global__ void __launch_bounds__(THREADS, 5)
obelisk_kernel(const float* __restrict__ vol,
               const float* __restrict__ xyz,
               const float* __restrict__ Amat,
               const float* __restrict__ W6,
               float* __restrict__ out)
{
    __shared__ float2 brick2[BRICK_E];   // 38.5KB static
    __shared__ float sP[12];
    __shared__ int   sBox[4];            // xlo,ylo,zlo,mode
    __shared__ float sRed[6*8];

    const int tid  = threadIdx.x;
    const int lane = tid & 31;
    const int wid  = tid >> 5;
    const int blk  = blockIdx.x;
    const int pt   = blk >> 1;
    const int kh   = blk & 1;
    const int b    = pt >> 9;
    const int f    = pt & (FEATS - 1);
    const int k0   = kh * KPB;

    if (tid == 0) {
        float x0 = xyz[pt*3+0], x1 = xyz[pt*3+1], x2 = xyz[pt*3+2];
        sP[0] = (x0 + 1.f) * 48.f - 0.5f;
        sP[1] = (x1 + 1.f) * 48.f - 0.5f;
        sP[2] = (x2 + 1.f) * 48.f - 0.5f;
        const float* Ar = Amat + pt * 9;
        sP[3] = 48.f*Ar[6]; sP[4]  = 48.f*Ar[7]; sP[5]  = 48.f*Ar[8];  // x row
        sP[6] = 48.f*Ar[3]; sP[7]  = 48.f*Ar[4]; sP[8]  = 48.f*Ar[5];  // y row
        sP[9] = 48.f*Ar[0]; sP[10] = 48.f*Ar[1]; sP[11] = 48.f*Ar[2];  // z row
    }
    __syncthreads();

    const float bx = sP[0], by = sP[1], bz = sP[2];
    const float ax0 = sP[3], ax1 = sP[4],  ax2 = sP[5];
    const float ay0 = sP[6], ay1 = sP[7],  ay2 = sP[8];
    const float az0 = sP[9], az1 = sP[10], az2 = sP[11];

    // ---------------- Pass 1: bbox of all sample coords (same FP exprs as pass 2)
    float mnx = 1e30f, mxx = -1e30f;
    float mny = 1e30f, mxy = -1e30f;
    float mnz = 1e30f, mxz = -1e30f;
    #pragma unroll
    for (int it = 0; it < 2; it++) {
        int k = k0 + it*THREADS + tid;
        #pragma unroll
        for (int s = 0; s < 2; s++) {
            const float* wp = W6 + s*3*KTOT + k;
            float w0 = __ldg(wp);
            float w1 = __ldg(wp + KTOT);
            float w2 = __ldg(wp + 2*KTOT);
            float px = fmaf(ax0, w0, fmaf(ax1, w1, fmaf(ax2, w2, bx)));
            float py = fmaf(ay0, w0, fmaf(ay1, w1, fmaf(ay2, w2, by)));
            float pz = fmaf(az0, w0, fmaf(az1, w1, fmaf(az2, w2, bz)));
            mnx = fminf(mnx, px); mxx = fmaxf(mxx, px);
            mny = fminf(mny, py); mxy = fmaxf(mxy, py);
            mnz = fminf(mnz, pz); mxz = fmaxf(mxz, pz);
        }
    }
    float r0 = mnx, r1 = -mxx, r2 = mny, r3 = -mxy, r4 = mnz, r5 = -mxz;
    #pragma unroll
    for (int o = 16; o > 0; o >>= 1) {
        r0 = fminf(r0, __shfl_xor_sync(0xffffffffu, r0, o));
        r1 = fminf(r1, __shfl_xor_sync(0xffffffffu, r1, o));
        r2 = fminf(r2, __shfl_xor_sync(0xffffffffu, r2, o));
        r3 = fminf(r3, __shfl_xor_sync(0xffffffffu, r3, o));
        r4 = fminf(r4, __shfl_xor_sync(0xffffffffu, r4, o));
        r5 = fminf(r5, __shfl_xor_sync(0xffffffffu, r5, o));
    }
    if (lane == 0) {
        sRed[0*8+wid] = r0; sRed[1*8+wid] = r1; sRed[2*8+wid] = r2;
        sRed[3*8+wid] = r3; sRed[4*8+wid] = r4; sRed[5*8+wid] = r5;
    }
    __syncthreads();
    if (tid == 0) {
        float m0 = sRed[0], m1 = sRed[8], m2 = sRed[16], m3 = sRed[24], m4 = sRed[32], m5 = sRed[40];
        #pragma unroll
        for (int i = 1; i < 8; i++) {
            m0 = fminf(m0, sRed[0*8+i]); m1 = fminf(m1, sRed[1*8+i]);
            m2 = fminf(m2, sRed[2*8+i]); m3 = fminf(m3, sRed[3*8+i]);
            m4 = fminf(m4, sRed[4*8+i]); m5 = fminf(m5, sRed[5*8+i]);
        }
        float MX = -m1, MY = -m3, MZ = -m5;
        int xlo = max(0, (int)floorf(m0));
        int xhi = min(DIM - 1, (int)floorf(MX) + 1);
        int ylo = max(0, (int)floorf(m2));
        int yhi = min(DIM - 1, (int)floorf(MY) + 1);
        int zlo = max(0, (int)floorf(m4));
        int zhi = min(DIM - 1, (int)floorf(MZ) + 1);
        int nx = xhi - xlo + 1, ny = yhi - ylo + 1, nz = zhi - zlo + 1;
        int mode;
        if (nx <= 0 || ny <= 0 || nz <= 0) mode = 2;                   // fully outside
        else if (nx <= NB && ny <= NB && nz <= NB) mode = 0;           // fixed 8^3 brick
        else mode = 1;                                                 // global fallback
        // anchor clamp: brick [lo, lo+7] always inside volume
        sBox[0] = min(xlo, DIM - NB);
        sBox[1] = min(ylo, DIM - NB);
        sBox[2] = min(zlo, DIM - NB);
        sBox[3] = mode;
    }
    __syncthreads();

    const int xlo = sBox[0], ylo = sBox[1], zlo = sBox[2];
    const int mode = sBox[3];

    const size_t out_base0 = (((size_t)b * C16) * FEATS + f) * KTOT;

    if (mode == 2) {
        #pragma unroll
        for (int it = 0; it < 2; it++) {
            int k = k0 + it*THREADS + tid;
            #pragma unroll
            for (int c = 0; c < C16; c++)
                out[out_base0 + (size_t)c * (FEATS*KTOT) + k] = 0.f;
        }
        return;
    }

    const float* volb = vol + (size_t)b * C16 * DHW;

    // ------- Brick load: 8x8x8 voxels x 8 channel-pairs, padded float2 layout -------
    if (mode == 0) {
        const float* src = volb + (size_t)zlo * HW + ylo * DIM + xlo;
        #pragma unroll
        for (int t = 0; t < (NPAIR*NB*NB*NB) / THREADS; t++) {   // 16 iters
            int m = t * THREADS + tid;
            int x  = m & 7;
            int y  = (m >> 3) & 7;
            int z  = (m >> 6) & 7;
            int c2 = m >> 9;
            const float* s0 = src + (size_t)(2*c2) * DHW + z * HW + y * DIM + x;
            float2 v;
            v.x = __ldg(s0);
            v.y = __ldg(s0 + DHW);
            brick2[c2 * PSV + z * SZ + y * SY + x] = v;
        }
    }
    __syncthreads();

    // ---------------- Main sampling loop ----------------
    if (mode == 0) {
        #pragma unroll
        for (int it = 0; it < 2; it++) {
            int k = k0 + it*THREADS + tid;
            float acc[C16];
            #pragma unroll
            for (int c = 0; c < C16; c++) acc[c] = 0.f;

            #pragma unroll
            for (int s = 0; s < 2; s++) {
                const float* wp = W6 + s*3*KTOT + k;
                float w0 = __ldg(wp);
                float w1 = __ldg(wp + KTOT);
                float w2 = __ldg(wp + 2*KTOT);
                float px = fmaf(ax0, w0, fmaf(ax1, w1, fmaf(ax2, w2, bx)));
                float py = fmaf(ay0, w0, fmaf(ay1, w1, fmaf(ay2, w2, by)));
                float pz = fmaf(az0, w0, fmaf(az1, w1, fmaf(az2, w2, bz)));
                float fx = floorf(px), fy = floorf(py), fz = floorf(pz);
                float tx = px - fx, ty = py - fy, tz = pz - fz;
                int jx0 = (int)fx - xlo, jy0 = (int)fy - ylo, jz0 = (int)fz - zlo;
                int jx1 = jx0 + 1, jy1 = jy0 + 1, jz1 = jz0 + 1;
                float wx0 = 1.f - tx, wx1 = tx;
                float wy0 = 1.f - ty, wy1 = ty;
                float wz0 = 1.f - tz, wz1 = tz;
                // out-of-brick == out-of-volume: zero weight + clamp index
                if ((unsigned)jx0 >= NB) { wx0 = 0.f; jx0 = 0; }
                if ((unsigned)jx1 >= NB) { wx1 = 0.f; jx1 = 0; }
                if ((unsigned)jy0 >= NB) { wy0 = 0.f; jy0 = 0; }
                if ((unsigned)jy1 >= NB) { wy1 = 0.f; jy1 = 0; }
                if ((unsigned)jz0 >= NB) { wz0 = 0.f; jz0 = 0; }
                if ((unsigned)jz1 >= NB) { wz1 = 0.f; jz1 = 0; }
                float sg = s ? -1.f : 1.f;
                float wzy00 = wz0*wy0*sg, wzy01 = wz0*wy1*sg;
                float wzy10 = wz1*wy0*sg, wzy11 = wz1*wy1*sg;
                int r00 = jz0*SZ + jy0*SY, r01 = jz0*SZ + jy1*SY;
                int r10 = jz1*SZ + jy0*SY, r11 = jz1*SZ + jy1*SY;
                int offs[8] = { r00+jx0, r00+jx1, r01+jx0, r01+jx1,
                                r10+jx0, r10+jx1, r11+jx0, r11+jx1 };
                float wgt[8] = { wzy00*wx0, wzy00*wx1, wzy01*wx0, wzy01*wx1,
                                 wzy10*wx0, wzy10*wx1, wzy11*wx0, wzy11*wx1 };
                #pragma unroll
                for (int j = 0; j < 8; j++) {
                    const float2* pj = brick2 + offs[j];   // one address per corner
                    float w = wgt[j];
                    #pragma unroll
                    for (int c2 = 0; c2 < NPAIR; c2++) {   // LDS.64, immediate c2*PSV*8
                        float2 v = pj[c2 * PSV];
                        acc[2*c2]   = fmaf(w, v.x, acc[2*c2]);
                        acc[2*c2+1] = fmaf(w, v.y, acc[2*c2+1]);
                    }
                }
            }
            #pragma unroll
            for (int c = 0; c < C16; c++)
                out[out_base0 + (size_t)c * (FEATS*KTOT) + k] = acc[c];
        }
    } else {
        // mode 1: rare oversized bbox -> direct global gathers
        #pragma unroll
        for (int it = 0; it < 2; it++) {
            int k = k0 + it*THREADS + tid;
            float acc[C16];
            #pragma unroll
            for (int c = 0; c < C16; c++) acc[c] = 0.f;

            #pragma unroll
            for (int s = 0; s < 2; s++) {
                const float* wp = W6 + s*3*KTOT + k;
                float w0 = __ldg(wp);
                float w1 = __ldg(wp + KTOT);
                float w2 = __ldg(wp + 2*KTOT);
                float px = fmaf(ax0, w0, fmaf(ax1, w1, fmaf(ax2, w2, bx)));
                float py = fmaf(ay0, w0, fmaf(ay1, w1, fmaf(ay2, w2, by)));
                float pz = fmaf(az0, w0, fmaf(az1, w1, fmaf(az2, w2, bz)));
                float fx = floorf(px), fy = floorf(py), fz = floorf(pz);
                float tx = px - fx, ty = py - fy, tz = pz - fz;
                int jx0 = (int)fx, jy0 = (int)fy, jz0 = (int)fz;
                int jx1 = jx0 + 1, jy1 = jy0 + 1, jz1 = jz0 + 1;
                float wx0 = 1.f - tx, wx1 = tx;
                float wy0 = 1.f - ty, wy1 = ty;
                float wz0 = 1.f - tz, wz1 = tz;
                if ((unsigned)jx0 >= (unsigned)DIM) { wx0 = 0.f; jx0 = 0; }
                if ((unsigned)jx1 >= (unsigned)DIM) { wx1 = 0.f; jx1 = 0; }
                if ((unsigned)jy0 >= (unsigned)DIM) { wy0 = 0.f; jy0 = 0; }
                if ((unsigned)jy1 >= (unsigned)DIM) { wy1 = 0.f; jy1 = 0; }
                if ((unsigned)jz0 >= (unsigned)DIM) { wz0 = 0.f; jz0 = 0; }
                if ((unsigned)jz1 >= (unsigned)DIM) { wz1 = 0.f; jz1 = 0; }
                float sg = s ? -1.f : 1.f;
                float wzy00 = wz0*wy0*sg, wzy01 = wz0*wy1*sg;
                float wzy10 = wz1*wy0*sg, wzy11 = wz1*wy1*sg;
                int r00 = jz0*HW + jy0*DIM, r01 = jz0*HW + jy1*DIM;
                int r10 = jz1*HW + jy0*DIM, r11 = jz1*HW + jy1*DIM;
                int offs[8] = { r00+jx0, r00+jx1, r01+jx0, r01+jx1,
                                r10+jx0, r10+jx1, r11+jx0, r11+jx1 };
                float wgt[8] = { wzy00*wx0, wzy00*wx1, wzy01*wx0, wzy01*wx1,
                                 wzy10*wx0, wzy10*wx1, wzy11*wx0, wzy11*wx1 };
                #pragma unroll
                for (int j = 0; j < 8; j++) {
                    const float* pj = volb + offs[j];
                    float w = wgt[j];
                    #pragma unroll
                    for (int c = 0; c < C16; c++)
                        acc[c] = fmaf(w, __ldg(pj + (size_t)c * DHW), acc[c]);
                }
            }
            #pragma unroll
            for (int c = 0; c < C16; c++)
                out[out_base0 + (size_t)c * (FEATS*KTOT) + k] = acc[c];
        }
    }
}

extern "C" void kernel_launch(void* const* d_in, const int* in_sizes, int n_in,
                              void* d_out, int out_size)
{
    const float* vol  = (const float*)d_in[0];  // [2,16,96,96,96]
    const float* xyz  = (const float*)d_in[1];  // [2,512,3]
    const float* Amat = (const float*)d_in[2];  // [1024,3,3]
    const float* W6   = (const float*)d_in[3];  // [6,1024]
    float* out = (float*)d_out;                 // [2, 16*512, 1024]

    const int nblocks = 2 * 2 * FEATS;          // 2048
    obelisk_kernel<<<nblocks, THREADS>>>(vol, xyz, Amat, W6, out);
}

// round 7
// speedup vs baseline: 1.0204x; 1.0204x over previous
#include <cuda_runtime.h>

#define THREADS 256
#define C16 16
#define DIM 96
#define HW (DIM*DIM)
#define DHW (DIM*DIM*DIM)
#define FEATS 512
#define KTOT 1024
#define KPB 512            // k per block (KSPLIT=2)
#define NB 8               // fixed brick edge
// padded scalar strides: x=1, y=9, z=77
// bank = (13*jz + 9*jy + jx) mod 32 -> nonzero for every |delta|<=1 neighbor offset
#define SY 9
#define SZ 77
#define PSV (NB*SZ)        // 616 floats per channel slab
#define BRICK_F (C16*PSV)  // 9856 floats = 38.5KB

__global__ void __launch_bounds__(THREADS, 5)
obelisk_kernel(const float* __restrict__ vol,
               const float* __restrict__ xyz,
               const float* __restrict__ Amat,
               const float* __restrict__ W6,
               float* __restrict__ out)
{
    __shared__ float brick[BRICK_F];   // 38.5KB static
    __shared__ float sP[12];
    __shared__ int   sBox[4];          // xlo,ylo,zlo,mode
    __shared__ float sRed[6*8];

    const int tid  = threadIdx.x;
    const int lane = tid & 31;
    const int wid  = tid >> 5;
    const int blk  = blockIdx.x;
    const int pt   = blk >> 1;
    const int kh   = blk & 1;
    const int b    = pt >> 9;
    const int f    = pt & (FEATS - 1);
    const int k0   = kh * KPB;

    if (tid == 0) {
        float x0 = xyz[pt*3+0], x1 = xyz[pt*3+1], x2 = xyz[pt*3+2];
        sP[0] = (x0 + 1.f) * 48.f - 0.5f;
        sP[1] = (x1 + 1.f) * 48.f - 0.5f;
        sP[2] = (x2 + 1.f) * 48.f - 0.5f;
        const float* Ar = Amat + pt * 9;
        sP[3] = 48.f*Ar[6]; sP[4]  = 48.f*Ar[7]; sP[5]  = 48.f*Ar[8];  // x row
        sP[6] = 48.f*Ar[3]; sP[7]  = 48.f*Ar[4]; sP[8]  = 48.f*Ar[5];  // y row
        sP[9] = 48.f*Ar[0]; sP[10] = 48.f*Ar[1]; sP[11] = 48.f*Ar[2];  // z row
    }
    __syncthreads();

    const float bx = sP[0], by = sP[1], bz = sP[2];
    const float ax0 = sP[3], ax1 = sP[4],  ax2 = sP[5];
    const float ay0 = sP[6], ay1 = sP[7],  ay2 = sP[8];
    const float az0 = sP[9], az1 = sP[10], az2 = sP[11];

    // ---------------- Pass 1: bbox of all sample coords (same FP exprs as pass 2)
    float mnx = 1e30f, mxx = -1e30f;
    float mny = 1e30f, mxy = -1e30f;
    float mnz = 1e30f, mxz = -1e30f;
    #pragma unroll
    for (int it = 0; it < 2; it++) {
        int k = k0 + it*THREADS + tid;
        #pragma unroll
        for (int s = 0; s < 2; s++) {
            const float* wp = W6 + s*3*KTOT + k;
            float w0 = __ldg(wp);
            float w1 = __ldg(wp + KTOT);
            float w2 = __ldg(wp + 2*KTOT);
            float px = fmaf(ax0, w0, fmaf(ax1, w1, fmaf(ax2, w2, bx)));
            float py = fmaf(ay0, w0, fmaf(ay1, w1, fmaf(ay2, w2, by)));
            float pz = fmaf(az0, w0, fmaf(az1, w1, fmaf(az2, w2, bz)));
            mnx = fminf(mnx, px); mxx = fmaxf(mxx, px);
            mny = fminf(mny, py); mxy = fmaxf(mxy, py);
            mnz = fminf(mnz, pz); mxz = fmaxf(mxz, pz);
        }
    }
    float r0 = mnx, r1 = -mxx, r2 = mny, r3 = -mxy, r4 = mnz, r5 = -mxz;
    #pragma unroll
    for (int o = 16; o > 0; o >>= 1) {
        r0 = fminf(r0, __shfl_xor_sync(0xffffffffu, r0, o));
        r1 = fminf(r1, __shfl_xor_sync(0xffffffffu, r1, o));
        r2 = fminf(r2, __shfl_xor_sync(0xffffffffu, r2, o));
        r3 = fminf(r3, __shfl_xor_sync(0xffffffffu, r3, o));
        r4 = fminf(r4, __shfl_xor_sync(0xffffffffu, r4, o));
        r5 = fminf(r5, __shfl_xor_sync(0xffffffffu, r5, o));
    }
    if (lane == 0) {
        sRed[0*8+wid] = r0; sRed[1*8+wid] = r1; sRed[2*8+wid] = r2;
        sRed[3*8+wid] = r3; sRed[4*8+wid] = r4; sRed[5*8+wid] = r5;
    }
    __syncthreads();
    if (tid == 0) {
        float m0 = sRed[0], m1 = sRed[8], m2 = sRed[16], m3 = sRed[24], m4 = sRed[32], m5 = sRed[40];
        #pragma unroll
        for (int i = 1; i < 8; i++) {
            m0 = fminf(m0, sRed[0*8+i]); m1 = fminf(m1, sRed[1*8+i]);
            m2 = fminf(m2, sRed[2*8+i]); m3 = fminf(m3, sRed[3*8+i]);
            m4 = fminf(m4, sRed[4*8+i]); m5 = fminf(m5, sRed[5*8+i]);
        }
        float MX = -m1, MY = -m3, MZ = -m5;
        int xlo = max(0, (int)floorf(m0));
        int xhi = min(DIM - 1, (int)floorf(MX) + 1);
        int ylo = max(0, (int)floorf(m2));
        int yhi = min(DIM - 1, (int)floorf(MY) + 1);
        int zlo = max(0, (int)floorf(m4));
        int zhi = min(DIM - 1, (int)floorf(MZ) + 1);
        int nx = xhi - xlo + 1, ny = yhi - ylo + 1, nz = zhi - zlo + 1;
        int mode;
        if (nx <= 0 || ny <= 0 || nz <= 0) mode = 2;                   // fully outside
        else if (nx <= NB && ny <= NB && nz <= NB) mode = 0;           // fixed 8^3 brick
        else mode = 1;                                                 // global fallback
        // anchor clamp: brick [lo, lo+7] always inside volume
        sBox[0] = min(xlo, DIM - NB);
        sBox[1] = min(ylo, DIM - NB);
        sBox[2] = min(zlo, DIM - NB);
        sBox[3] = mode;
    }
    __syncthreads();

    const int xlo = sBox[0], ylo = sBox[1], zlo = sBox[2];
    const int mode = sBox[3];

    const size_t out_base0 = (((size_t)b * C16) * FEATS + f) * KTOT;

    if (mode == 2) {
        #pragma unroll
        for (int it = 0; it < 2; it++) {
            int k = k0 + it*THREADS + tid;
            #pragma unroll
            for (int c = 0; c < C16; c++)
                out[out_base0 + (size_t)c * (FEATS*KTOT) + k] = 0.f;
        }
        return;
    }

    const float* volb = vol + (size_t)b * C16 * DHW;

    // ------- Brick load: fixed 8x8x8 x 16ch, padded scalar layout -------
    if (mode == 0) {
        const float* src = volb + (size_t)zlo * HW + ylo * DIM + xlo;
        #pragma unroll
        for (int t = 0; t < (C16*NB*NB*NB) / THREADS; t++) {   // 32 iters
            int m = t * THREADS + tid;
            int x = m & 7;
            int y = (m >> 3) & 7;
            int z = (m >> 6) & 7;
            int c = m >> 9;
            brick[c * PSV + z * SZ + y * SY + x] =
                __ldg(src + (size_t)c * DHW + z * HW + y * DIM + x);
        }
    }
    __syncthreads();

    // ---------------- Main sampling loop ----------------
    if (mode == 0) {
        #pragma unroll
        for (int it = 0; it < 2; it++) {
            int k = k0 + it*THREADS + tid;
            float acc[C16];
            #pragma unroll
            for (int c = 0; c < C16; c++) acc[c] = 0.f;

            #pragma unroll
            for (int s = 0; s < 2; s++) {
                const float* wp = W6 + s*3*KTOT + k;
                float w0 = __ldg(wp);
                float w1 = __ldg(wp + KTOT);
                float w2 = __ldg(wp + 2*KTOT);
                float px = fmaf(ax0, w0, fmaf(ax1, w1, fmaf(ax2, w2, bx)));
                float py = fmaf(ay0, w0, fmaf(ay1, w1, fmaf(ay2, w2, by)));
                float pz = fmaf(az0, w0, fmaf(az1, w1, fmaf(az2, w2, bz)));
                float fx = floorf(px), fy = floorf(py), fz = floorf(pz);
                float tx = px - fx, ty = py - fy, tz = pz - fz;
                int jx0 = (int)fx - xlo, jy0 = (int)fy - ylo, jz0 = (int)fz - zlo;
                int jx1 = jx0 + 1, jy1 = jy0 + 1, jz1 = jz0 + 1;
                float wx0 = 1.f - tx, wx1 = tx;
                float wy0 = 1.f - ty, wy1 = ty;
                float wz0 = 1.f - tz, wz1 = tz;
                // out-of-brick == out-of-volume: zero weight + clamp index
                if ((unsigned)jx0 >= NB) { wx0 = 0.f; jx0 = 0; }
                if ((unsigned)jx1 >= NB) { wx1 = 0.f; jx1 = 0; }
                if ((unsigned)jy0 >= NB) { wy0 = 0.f; jy0 = 0; }
                if ((unsigned)jy1 >= NB) { wy1 = 0.f; jy1 = 0; }
                if ((unsigned)jz0 >= NB) { wz0 = 0.f; jz0 = 0; }
                if ((unsigned)jz1 >= NB) { wz1 = 0.f; jz1 = 0; }
                float sg = s ? -1.f : 1.f;
                float wzy00 = wz0*wy0*sg, wzy01 = wz0*wy1*sg;
                float wzy10 = wz1*wy0*sg, wzy11 = wz1*wy1*sg;
                int r00 = jz0*SZ + jy0*SY, r01 = jz0*SZ + jy1*SY;
                int r10 = jz1*SZ + jy0*SY, r11 = jz1*SZ + jy1*SY;
                int offs[8] = { r00+jx0, r00+jx1, r01+jx0, r01+jx1,
                                r10+jx0, r10+jx1, r11+jx0, r11+jx1 };
                float wgt[8] = { wzy00*wx0, wzy00*wx1, wzy01*wx0, wzy01*wx1,
                                 wzy10*wx0, wzy10*wx1, wzy11*wx0, wzy11*wx1 };
                #pragma unroll
                for (int j = 0; j < 8; j++) {
                    const float* pj = brick + offs[j];   // one address per corner
                    float w = wgt[j];
                    #pragma unroll
                    for (int c = 0; c < C16; c++)        // LDS.32 with immediate c*PSV*4
                        acc[c] = fmaf(w, pj[c * PSV], acc[c]);
                }
            }
            #pragma unroll
            for (int c = 0; c < C16; c++)
                out[out_base0 + (size_t)c * (FEATS*KTOT) + k] = acc[c];
        }
    } else {
        // mode 1: rare oversized bbox -> direct global gathers
        #pragma unroll
        for (int it = 0; it < 2; it++) {
            int k = k0 + it*THREADS + tid;
            float acc[C16];
            #pragma unroll
            for (int c = 0; c < C16; c++) acc[c] = 0.f;

            #pragma unroll
            for (int s = 0; s < 2; s++) {
                const float* wp = W6 + s*3*KTOT + k;
                float w0 = __ldg(wp);
                float w1 = __ldg(wp + KTOT);
                float w2 = __ldg(wp + 2*KTOT);
                float px = fmaf(ax0, w0, fmaf(ax1, w1, fmaf(ax2, w2, bx)));
                float py = fmaf(ay0, w0, fmaf(ay1, w1, fmaf(ay2, w2, by)));
                float pz = fmaf(az0, w0, fmaf(az1, w1, fmaf(az2, w2, bz)));
                float fx = floorf(px), fy = floorf(py), fz = floorf(pz);
                float tx = px - fx, ty = py - fy, tz = pz - fz;
                int jx0 = (int)fx, jy0 = (int)fy, jz0 = (int)fz;
                int jx1 = jx0 + 1, jy1 = jy0 + 1, jz1 = jz0 + 1;
                float wx0 = 1.f - tx, wx1 = tx;
                float wy0 = 1.f - ty, wy1 = ty;
                float wz0 = 1.f - tz, wz1 = tz;
                if ((unsigned)jx0 >= (unsigned)DIM) { wx0 = 0.f; jx0 = 0; }
                if ((unsigned)jx1 >= (unsigned)DIM) { wx1 = 0.f; jx1 = 0; }
                if ((unsigned)jy0 >= (unsigned)DIM) { wy0 = 0.f; jy0 = 0; }
                if ((unsigned)jy1 >= (unsigned)DIM) { wy1 = 0.f; jy1 = 0; }
                if ((unsigned)jz0 >= (unsigned)DIM) { wz0 = 0.f; jz0 = 0; }
                if ((unsigned)jz1 >= (unsigned)DIM) { wz1 = 0.f; jz1 = 0; }
                float sg = s ? -1.f : 1.f;
                float wzy00 = wz0*wy0*sg, wzy01 = wz0*wy1*sg;
                float wzy10 = wz1*wy0*sg, wzy11 = wz1*wy1*sg;
                int r00 = jz0*HW + jy0*DIM, r01 = jz0*HW + jy1*DIM;
                int r10 = jz1*HW + jy0*DIM, r11 = jz1*HW + jy1*DIM;
                int offs[8] = { r00+jx0, r00+jx1, r01+jx0, r01+jx1,
                                r10+jx0, r10+jx1, r11+jx0, r11+jx1 };
                float wgt[8] = { wzy00*wx0, wzy00*wx1, wzy01*wx0, wzy01*wx1,
                                 wzy10*wx0, wzy10*wx1, wzy11*wx0, wzy11*wx1 };
                #pragma unroll
                for (int j = 0; j < 8; j++) {
                    const float* pj = volb + offs[j];
                    float w = wgt[j];
                    #pragma unroll
                    for (int c = 0; c < C16; c++)
                        acc[c] = fmaf(w, __ldg(pj + (size_t)c * DHW), acc[c]);
                }
            }
            #pragma unroll
            for (int c = 0; c < C16; c++)
                out[out_base0 + (size_t)c * (FEATS*KTOT) + k] = acc[c];
        }
    }
}

extern "C" void kernel_launch(void* const* d_in, const int* in_sizes, int n_in,
                              void* d_out, int out_size)
{
    const float* vol  = (const float*)d_in[0];  // [2,16,96,96,96]
    const float* xyz  = (const float*)d_in[1];  // [2,512,3]
    const float* Amat = (const float*)d_in[2];  // [1024,3,3]
    const float* W6   = (const float*)d_in[3];  // [6,1024]
    float* out = (float*)d_out;                 // [2, 16*512, 1024]

    const int nblocks = 2 * 2 * FEATS;          // 2048
    obelisk_kernel<<<nblocks, THREADS>>>(vol, xyz, Amat, W6, out);
}

// round 8
// speedup vs baseline: 1.3036x; 1.2775x over previous
#include <cuda_runtime.h>

#define THREADS 256
#define C16 16
#define DIM 96
#define HW (DIM*DIM)
#define DHW (DIM*DIM*DIM)
#define FEATS 512
#define KTOT 1024
#define KPB 512            // k per block (KSPLIT=2)
#define NB 8               // fixed brick edge
// padded scalar strides: x=1, y=9, z=77
// bank = (13*jz + 9*jy + jx) mod 32 -> nonzero for every |delta|<=1 neighbor offset
#define SY 9
#define SZ 77
#define PSV (NB*SZ)        // 616 floats per channel slab
#define BRICK_F (C16*PSV)  // 9856 floats = 38.5KB

__global__ void __launch_bounds__(THREADS, 4)
obelisk_kernel(const float* __restrict__ vol,
               const float* __restrict__ xyz,
               const float* __restrict__ Amat,
               const float* __restrict__ W6,
               float* __restrict__ out)
{
    __shared__ float brick[BRICK_F];   // 38.5KB static
    __shared__ float sP[12];
    __shared__ int   sBox[4];          // xlo,ylo,zlo,mode
    __shared__ float sRed[6*8];

    const int tid  = threadIdx.x;
    const int lane = tid & 31;
    const int wid  = tid >> 5;
    const int blk  = blockIdx.x;
    const int pt   = blk >> 1;
    const int kh   = blk & 1;
    const int b    = pt >> 9;
    const int f    = pt & (FEATS - 1);
    const int k0   = kh * KPB;

    if (tid == 0) {
        float x0 = xyz[pt*3+0], x1 = xyz[pt*3+1], x2 = xyz[pt*3+2];
        sP[0] = (x0 + 1.f) * 48.f - 0.5f;
        sP[1] = (x1 + 1.f) * 48.f - 0.5f;
        sP[2] = (x2 + 1.f) * 48.f - 0.5f;
        const float* Ar = Amat + pt * 9;
        sP[3] = 48.f*Ar[6]; sP[4]  = 48.f*Ar[7]; sP[5]  = 48.f*Ar[8];  // x row
        sP[6] = 48.f*Ar[3]; sP[7]  = 48.f*Ar[4]; sP[8]  = 48.f*Ar[5];  // y row
        sP[9] = 48.f*Ar[0]; sP[10] = 48.f*Ar[1]; sP[11] = 48.f*Ar[2];  // z row
    }
    __syncthreads();

    const float bx = sP[0], by = sP[1], bz = sP[2];
    const float ax0 = sP[3], ax1 = sP[4],  ax2 = sP[5];
    const float ay0 = sP[6], ay1 = sP[7],  ay2 = sP[8];
    const float az0 = sP[9], az1 = sP[10], az2 = sP[11];

    // ---------------- Pass 1: bbox of all sample coords (same FP exprs as pass 2)
    float mnx = 1e30f, mxx = -1e30f;
    float mny = 1e30f, mxy = -1e30f;
    float mnz = 1e30f, mxz = -1e30f;
    #pragma unroll
    for (int it = 0; it < 2; it++) {
        int k = k0 + it*THREADS + tid;
        #pragma unroll
        for (int s = 0; s < 2; s++) {
            const float* wp = W6 + s*3*KTOT + k;
            float w0 = __ldg(wp);
            float w1 = __ldg(wp + KTOT);
            float w2 = __ldg(wp + 2*KTOT);
            float px = fmaf(ax0, w0, fmaf(ax1, w1, fmaf(ax2, w2, bx)));
            float py = fmaf(ay0, w0, fmaf(ay1, w1, fmaf(ay2, w2, by)));
            float pz = fmaf(az0, w0, fmaf(az1, w1, fmaf(az2, w2, bz)));
            mnx = fminf(mnx, px); mxx = fmaxf(mxx, px);
            mny = fminf(mny, py); mxy = fmaxf(mxy, py);
            mnz = fminf(mnz, pz); mxz = fmaxf(mxz, pz);
        }
    }
    float r0 = mnx, r1 = -mxx, r2 = mny, r3 = -mxy, r4 = mnz, r5 = -mxz;
    #pragma unroll
    for (int o = 16; o > 0; o >>= 1) {
        r0 = fminf(r0, __shfl_xor_sync(0xffffffffu, r0, o));
        r1 = fminf(r1, __shfl_xor_sync(0xffffffffu, r1, o));
        r2 = fminf(r2, __shfl_xor_sync(0xffffffffu, r2, o));
        r3 = fminf(r3, __shfl_xor_sync(0xffffffffu, r3, o));
        r4 = fminf(r4, __shfl_xor_sync(0xffffffffu, r4, o));
        r5 = fminf(r5, __shfl_xor_sync(0xffffffffu, r5, o));
    }
    if (lane == 0) {
        sRed[0*8+wid] = r0; sRed[1*8+wid] = r1; sRed[2*8+wid] = r2;
        sRed[3*8+wid] = r3; sRed[4*8+wid] = r4; sRed[5*8+wid] = r5;
    }
    __syncthreads();
    if (tid == 0) {
        float m0 = sRed[0], m1 = sRed[8], m2 = sRed[16], m3 = sRed[24], m4 = sRed[32], m5 = sRed[40];
        #pragma unroll
        for (int i = 1; i < 8; i++) {
            m0 = fminf(m0, sRed[0*8+i]); m1 = fminf(m1, sRed[1*8+i]);
            m2 = fminf(m2, sRed[2*8+i]); m3 = fminf(m3, sRed[3*8+i]);
            m4 = fminf(m4, sRed[4*8+i]); m5 = fminf(m5, sRed[5*8+i]);
        }
        float MX = -m1, MY = -m3, MZ = -m5;
        int xlo = max(0, (int)floorf(m0));
        int xhi = min(DIM - 1, (int)floorf(MX) + 1);
        int ylo = max(0, (int)floorf(m2));
        int yhi = min(DIM - 1, (int)floorf(MY) + 1);
        int zlo = max(0, (int)floorf(m4));
        int zhi = min(DIM - 1, (int)floorf(MZ) + 1);
        int nx = xhi - xlo + 1, ny = yhi - ylo + 1, nz = zhi - zlo + 1;
        int mode;
        if (nx <= 0 || ny <= 0 || nz <= 0) mode = 2;                   // fully outside
        else if (nx <= NB && ny <= NB && nz <= NB) mode = 0;           // fixed 8^3 brick
        else mode = 1;                                                 // global fallback
        // anchor clamp: brick [lo, lo+7] always inside volume
        sBox[0] = min(xlo, DIM - NB);
        sBox[1] = min(ylo, DIM - NB);
        sBox[2] = min(zlo, DIM - NB);
        sBox[3] = mode;
    }
    __syncthreads();

    const int xlo = sBox[0], ylo = sBox[1], zlo = sBox[2];
    const int mode = sBox[3];

    const size_t out_base0 = (((size_t)b * C16) * FEATS + f) * KTOT;

    if (mode == 2) {
        #pragma unroll
        for (int it = 0; it < 2; it++) {
            int k = k0 + it*THREADS + tid;
            #pragma unroll
            for (int c = 0; c < C16; c++)
                out[out_base0 + (size_t)c * (FEATS*KTOT) + k] = 0.f;
        }
        return;
    }

    const float* volb = vol + (size_t)b * C16 * DHW;

    // ------- Brick load: fixed 8x8x8 x 16ch, padded scalar layout -------
    if (mode == 0) {
        const float* src = volb + (size_t)zlo * HW + ylo * DIM + xlo;
        #pragma unroll
        for (int t = 0; t < (C16*NB*NB*NB) / THREADS; t++) {   // 32 iters
            int m = t * THREADS + tid;
            int x = m & 7;
            int y = (m >> 3) & 7;
            int z = (m >> 6) & 7;
            int c = m >> 9;
            brick[c * PSV + z * SZ + y * SY + x] =
                __ldg(src + (size_t)c * DHW + z * HW + y * DIM + x);
        }
    }
    __syncthreads();

    // ---------------- Main sampling loop ----------------
    if (mode == 0) {
        #pragma unroll
        for (int it = 0; it < 2; it++) {
            int k = k0 + it*THREADS + tid;
            float acc[C16];
            #pragma unroll
            for (int c = 0; c < C16; c++) acc[c] = 0.f;

            // load all 6 offset weights up front (batch both LDG latencies)
            float w0a = __ldg(W6 + k);
            float w1a = __ldg(W6 + KTOT + k);
            float w2a = __ldg(W6 + 2*KTOT + k);
            float w0b = __ldg(W6 + 3*KTOT + k);
            float w1b = __ldg(W6 + 4*KTOT + k);
            float w2b = __ldg(W6 + 5*KTOT + k);

            #pragma unroll
            for (int s = 0; s < 2; s++) {
                float w0 = s ? w0b : w0a;
                float w1 = s ? w1b : w1a;
                float w2 = s ? w2b : w2a;
                float px = fmaf(ax0, w0, fmaf(ax1, w1, fmaf(ax2, w2, bx)));
                float py = fmaf(ay0, w0, fmaf(ay1, w1, fmaf(ay2, w2, by)));
                float pz = fmaf(az0, w0, fmaf(az1, w1, fmaf(az2, w2, bz)));
                float fx = floorf(px), fy = floorf(py), fz = floorf(pz);
                float tx = px - fx, ty = py - fy, tz = pz - fz;
                int jx0 = (int)fx - xlo, jy0 = (int)fy - ylo, jz0 = (int)fz - zlo;
                int jx1 = jx0 + 1, jy1 = jy0 + 1, jz1 = jz0 + 1;
                float wx0 = 1.f - tx, wx1 = tx;
                float wy0 = 1.f - ty, wy1 = ty;
                float wz0 = 1.f - tz, wz1 = tz;
                // out-of-brick == out-of-volume: zero weight + clamp index
                if ((unsigned)jx0 >= NB) { wx0 = 0.f; jx0 = 0; }
                if ((unsigned)jx1 >= NB) { wx1 = 0.f; jx1 = 0; }
                if ((unsigned)jy0 >= NB) { wy0 = 0.f; jy0 = 0; }
                if ((unsigned)jy1 >= NB) { wy1 = 0.f; jy1 = 0; }
                if ((unsigned)jz0 >= NB) { wz0 = 0.f; jz0 = 0; }
                if ((unsigned)jz1 >= NB) { wz1 = 0.f; jz1 = 0; }
                float sg = s ? -1.f : 1.f;
                float wzy00 = wz0*wy0*sg, wzy01 = wz0*wy1*sg;
                float wzy10 = wz1*wy0*sg, wzy11 = wz1*wy1*sg;
                int r00 = jz0*SZ + jy0*SY, r01 = jz0*SZ + jy1*SY;
                int r10 = jz1*SZ + jy0*SY, r11 = jz1*SZ + jy1*SY;
                int offs[8] = { r00+jx0, r00+jx1, r01+jx0, r01+jx1,
                                r10+jx0, r10+jx1, r11+jx0, r11+jx1 };
                float wgt[8] = { wzy00*wx0, wzy00*wx1, wzy01*wx0, wzy01*wx1,
                                 wzy10*wx0, wzy10*wx1, wzy11*wx0, wzy11*wx1 };
                #pragma unroll
                for (int j = 0; j < 8; j++) {
                    const float* pj = brick + offs[j];   // one address per corner
                    float w = wgt[j];
                    #pragma unroll
                    for (int c = 0; c < C16; c++)        // LDS.32 with immediate c*PSV*4
                        acc[c] = fmaf(w, pj[c * PSV], acc[c]);
                }
            }
            #pragma unroll
            for (int c = 0; c < C16; c++)
                out[out_base0 + (size_t)c * (FEATS*KTOT) + k] = acc[c];
        }
    } else {
        // mode 1: rare oversized bbox -> direct global gathers
        #pragma unroll
        for (int it = 0; it < 2; it++) {
            int k = k0 + it*THREADS + tid;
            float acc[C16];
            #pragma unroll
            for (int c = 0; c < C16; c++) acc[c] = 0.f;

            #pragma unroll
            for (int s = 0; s < 2; s++) {
                const float* wp = W6 + s*3*KTOT + k;
                float w0 = __ldg(wp);
                float w1 = __ldg(wp + KTOT);
                float w2 = __ldg(wp + 2*KTOT);
                float px = fmaf(ax0, w0, fmaf(ax1, w1, fmaf(ax2, w2, bx)));
                float py = fmaf(ay0, w0, fmaf(ay1, w1, fmaf(ay2, w2, by)));
                float pz = fmaf(az0, w0, fmaf(az1, w1, fmaf(az2, w2, bz)));
                float fx = floorf(px), fy = floorf(py), fz = floorf(pz);
                float tx = px - fx, ty = py - fy, tz = pz - fz;
                int jx0 = (int)fx, jy0 = (int)fy, jz0 = (int)fz;
                int jx1 = jx0 + 1, jy1 = jy0 + 1, jz1 = jz0 + 1;
                float wx0 = 1.f - tx, wx1 = tx;
                float wy0 = 1.f - ty, wy1 = ty;
                float wz0 = 1.f - tz, wz1 = tz;
                if ((unsigned)jx0 >= (unsigned)DIM) { wx0 = 0.f; jx0 = 0; }
                if ((unsigned)jx1 >= (unsigned)DIM) { wx1 = 0.f; jx1 = 0; }
                if ((unsigned)jy0 >= (unsigned)DIM) { wy0 = 0.f; jy0 = 0; }
                if ((unsigned)jy1 >= (unsigned)DIM) { wy1 = 0.f; jy1 = 0; }
                if ((unsigned)jz0 >= (unsigned)DIM) { wz0 = 0.f; jz0 = 0; }
                if ((unsigned)jz1 >= (unsigned)DIM) { wz1 = 0.f; jz1 = 0; }
                float sg = s ? -1.f : 1.f;
                float wzy00 = wz0*wy0*sg, wzy01 = wz0*wy1*sg;
                float wzy10 = wz1*wy0*sg, wzy11 = wz1*wy1*sg;
                int r00 = jz0*HW + jy0*DIM, r01 = jz0*HW + jy1*DIM;
                int r10 = jz1*HW + jy0*DIM, r11 = jz1*HW + jy1*DIM;
                int offs[8] = { r00+jx0, r00+jx1, r01+jx0, r01+jx1,
                                r10+jx0, r10+jx1, r11+jx0, r11+jx1 };
                float wgt[8] = { wzy00*wx0, wzy00*wx1, wzy01*wx0, wzy01*wx1,
                                 wzy10*wx0, wzy10*wx1, wzy11*wx0, wzy11*wx1 };
                #pragma unroll
                for (int j = 0; j < 8; j++) {
                    const float* pj = volb + offs[j];
                    float w = wgt[j];
                    #pragma unroll
                    for (int c = 0; c < C16; c++)
                        acc[c] = fmaf(w, __ldg(pj + (size_t)c * DHW), acc[c]);
                }
            }
            #pragma unroll
            for (int c = 0; c < C16; c++)
                out[out_base0 + (size_t)c * (FEATS*KTOT) + k] = acc[c];
        }
    }
}

extern "C" void kernel_launch(void* const* d_in, const int* in_sizes, int n_in,
                              void* d_out, int out_size)
{
    const float* vol  = (const float*)d_in[0];  // [2,16,96,96,96]
    const float* xyz  = (const float*)d_in[1];  // [2,512,3]
    const float* Amat = (const float*)d_in[2];  // [1024,3,3]
    const float* W6   = (const float*)d_in[3];  // [6,1024]
    float* out = (float*)d_out;                 // [2, 16*512, 1024]

    const int nblocks = 2 * 2 * FEATS;          // 2048
    obelisk_kernel<<<nblocks, THREADS>>>(vol, xyz, Amat, W6, out);
}

// round 9
// speedup vs baseline: 1.5031x; 1.1530x over previous
#include <cuda_runtime.h>
#include <cuda_fp16.h>

#define THREADS 256
#define C16 16
#define DIM 96
#define HW (DIM*DIM)
#define DHW (DIM*DIM*DIM)
#define FEATS 512
#define KTOT 1024
#define KPB 512            // k per block (KSPLIT=2)
#define NB 8               // fixed brick edge
// padded strides in half2 (4B) units: x=1, y=9, z=77
// bank = (13*jz + 9*jy + jx) mod 32 -> nonzero for every |delta|<=1 neighbor offset
#define SY 9
#define SZ 77
#define PSV (NB*SZ)        // 616 half2 per channel-pair slab
#define NPAIR 8            // 16 channels = 8 half2 pairs
#define BRICK_E (NPAIR*PSV) // 4928 half2 = 19.7KB

__global__ void __launch_bounds__(THREADS, 4)
obelisk_kernel(const float* __restrict__ vol,
               const float* __restrict__ xyz,
               const float* __restrict__ Amat,
               const float* __restrict__ W6,
               float* __restrict__ out)
{
    __shared__ __half2 brick2[BRICK_E];   // 19.7KB static
    __shared__ float sP[12];
    __shared__ int   sBox[4];             // xlo,ylo,zlo,mode
    __shared__ float sRed[6*8];

    const int tid  = threadIdx.x;
    const int lane = tid & 31;
    const int wid  = tid >> 5;
    const int blk  = blockIdx.x;
    const int pt   = blk >> 1;
    const int kh   = blk & 1;
    const int b    = pt >> 9;
    const int f    = pt & (FEATS - 1);
    const int k0   = kh * KPB;

    if (tid == 0) {
        float x0 = xyz[pt*3+0], x1 = xyz[pt*3+1], x2 = xyz[pt*3+2];
        sP[0] = (x0 + 1.f) * 48.f - 0.5f;
        sP[1] = (x1 + 1.f) * 48.f - 0.5f;
        sP[2] = (x2 + 1.f) * 48.f - 0.5f;
        const float* Ar = Amat + pt * 9;
        sP[3] = 48.f*Ar[6]; sP[4]  = 48.f*Ar[7]; sP[5]  = 48.f*Ar[8];  // x row
        sP[6] = 48.f*Ar[3]; sP[7]  = 48.f*Ar[4]; sP[8]  = 48.f*Ar[5];  // y row
        sP[9] = 48.f*Ar[0]; sP[10] = 48.f*Ar[1]; sP[11] = 48.f*Ar[2];  // z row
    }
    __syncthreads();

    const float bx = sP[0], by = sP[1], bz = sP[2];
    const float ax0 = sP[3], ax1 = sP[4],  ax2 = sP[5];
    const float ay0 = sP[6], ay1 = sP[7],  ay2 = sP[8];
    const float az0 = sP[9], az1 = sP[10], az2 = sP[11];

    // ---------------- Pass 1: bbox of all sample coords (same FP exprs as pass 2)
    float mnx = 1e30f, mxx = -1e30f;
    float mny = 1e30f, mxy = -1e30f;
    float mnz = 1e30f, mxz = -1e30f;
    #pragma unroll
    for (int it = 0; it < 2; it++) {
        int k = k0 + it*THREADS + tid;
        #pragma unroll
        for (int s = 0; s < 2; s++) {
            const float* wp = W6 + s*3*KTOT + k;
            float w0 = __ldg(wp);
            float w1 = __ldg(wp + KTOT);
            float w2 = __ldg(wp + 2*KTOT);
            float px = fmaf(ax0, w0, fmaf(ax1, w1, fmaf(ax2, w2, bx)));
            float py = fmaf(ay0, w0, fmaf(ay1, w1, fmaf(ay2, w2, by)));
            float pz = fmaf(az0, w0, fmaf(az1, w1, fmaf(az2, w2, bz)));
            mnx = fminf(mnx, px); mxx = fmaxf(mxx, px);
            mny = fminf(mny, py); mxy = fmaxf(mxy, py);
            mnz = fminf(mnz, pz); mxz = fmaxf(mxz, pz);
        }
    }
    float r0 = mnx, r1 = -mxx, r2 = mny, r3 = -mxy, r4 = mnz, r5 = -mxz;
    #pragma unroll
    for (int o = 16; o > 0; o >>= 1) {
        r0 = fminf(r0, __shfl_xor_sync(0xffffffffu, r0, o));
        r1 = fminf(r1, __shfl_xor_sync(0xffffffffu, r1, o));
        r2 = fminf(r2, __shfl_xor_sync(0xffffffffu, r2, o));
        r3 = fminf(r3, __shfl_xor_sync(0xffffffffu, r3, o));
        r4 = fminf(r4, __shfl_xor_sync(0xffffffffu, r4, o));
        r5 = fminf(r5, __shfl_xor_sync(0xffffffffu, r5, o));
    }
    if (lane == 0) {
        sRed[0*8+wid] = r0; sRed[1*8+wid] = r1; sRed[2*8+wid] = r2;
        sRed[3*8+wid] = r3; sRed[4*8+wid] = r4; sRed[5*8+wid] = r5;
    }
    __syncthreads();
    if (tid == 0) {
        float m0 = sRed[0], m1 = sRed[8], m2 = sRed[16], m3 = sRed[24], m4 = sRed[32], m5 = sRed[40];
        #pragma unroll
        for (int i = 1; i < 8; i++) {
            m0 = fminf(m0, sRed[0*8+i]); m1 = fminf(m1, sRed[1*8+i]);
            m2 = fminf(m2, sRed[2*8+i]); m3 = fminf(m3, sRed[3*8+i]);
            m4 = fminf(m4, sRed[4*8+i]); m5 = fminf(m5, sRed[5*8+i]);
        }
        float MX = -m1, MY = -m3, MZ = -m5;
        int xlo = max(0, (int)floorf(m0));
        int xhi = min(DIM - 1, (int)floorf(MX) + 1);
        int ylo = max(0, (int)floorf(m2));
        int yhi = min(DIM - 1, (int)floorf(MY) + 1);
        int zlo = max(0, (int)floorf(m4));
        int zhi = min(DIM - 1, (int)floorf(MZ) + 1);
        int nx = xhi - xlo + 1, ny = yhi - ylo + 1, nz = zhi - zlo + 1;
        int mode;
        if (nx <= 0 || ny <= 0 || nz <= 0) mode = 2;                   // fully outside
        else if (nx <= NB && ny <= NB && nz <= NB) mode = 0;           // fixed 8^3 brick
        else mode = 1;                                                 // global fallback
        // anchor clamp: brick [lo, lo+7] always inside volume
        sBox[0] = min(xlo, DIM - NB);
        sBox[1] = min(ylo, DIM - NB);
        sBox[2] = min(zlo, DIM - NB);
        sBox[3] = mode;
    }
    __syncthreads();

    const int xlo = sBox[0], ylo = sBox[1], zlo = sBox[2];
    const int mode = sBox[3];

    const size_t out_base0 = (((size_t)b * C16) * FEATS + f) * KTOT;

    if (mode == 2) {
        #pragma unroll
        for (int it = 0; it < 2; it++) {
            int k = k0 + it*THREADS + tid;
            #pragma unroll
            for (int c = 0; c < C16; c++)
                out[out_base0 + (size_t)c * (FEATS*KTOT) + k] = 0.f;
        }
        return;
    }

    const float* volb = vol + (size_t)b * C16 * DHW;

    // ------- Brick load: 8x8x8 voxels x 8 channel-pairs, fp16x2 padded layout -------
    if (mode == 0) {
        const float* src = volb + (size_t)zlo * HW + ylo * DIM + xlo;
        #pragma unroll
        for (int t = 0; t < (NPAIR*NB*NB*NB) / THREADS; t++) {   // 16 iters
            int m = t * THREADS + tid;
            int x  = m & 7;
            int y  = (m >> 3) & 7;
            int z  = (m >> 6) & 7;
            int c2 = m >> 9;
            const float* s0 = src + (size_t)(2*c2) * DHW + z * HW + y * DIM + x;
            float vx = __ldg(s0);
            float vy = __ldg(s0 + DHW);
            brick2[c2 * PSV + z * SZ + y * SY + x] = __floats2half2_rn(vx, vy);
        }
    }
    __syncthreads();

    // ---------------- Main sampling loop ----------------
    if (mode == 0) {
        #pragma unroll
        for (int it = 0; it < 2; it++) {
            int k = k0 + it*THREADS + tid;
            float acc[C16];
            #pragma unroll
            for (int c = 0; c < C16; c++) acc[c] = 0.f;

            // load all 6 offset weights up front (batch both LDG latencies)
            float w0a = __ldg(W6 + k);
            float w1a = __ldg(W6 + KTOT + k);
            float w2a = __ldg(W6 + 2*KTOT + k);
            float w0b = __ldg(W6 + 3*KTOT + k);
            float w1b = __ldg(W6 + 4*KTOT + k);
            float w2b = __ldg(W6 + 5*KTOT + k);

            #pragma unroll
            for (int s = 0; s < 2; s++) {
                float w0 = s ? w0b : w0a;
                float w1 = s ? w1b : w1a;
                float w2 = s ? w2b : w2a;
                float px = fmaf(ax0, w0, fmaf(ax1, w1, fmaf(ax2, w2, bx)));
                float py = fmaf(ay0, w0, fmaf(ay1, w1, fmaf(ay2, w2, by)));
                float pz = fmaf(az0, w0, fmaf(az1, w1, fmaf(az2, w2, bz)));
                float fx = floorf(px), fy = floorf(py), fz = floorf(pz);
                float tx = px - fx, ty = py - fy, tz = pz - fz;
                int jx0 = (int)fx - xlo, jy0 = (int)fy - ylo, jz0 = (int)fz - zlo;
                int jx1 = jx0 + 1, jy1 = jy0 + 1, jz1 = jz0 + 1;
                float wx0 = 1.f - tx, wx1 = tx;
                float wy0 = 1.f - ty, wy1 = ty;
                float wz0 = 1.f - tz, wz1 = tz;
                // out-of-brick == out-of-volume: zero weight + clamp index
                if ((unsigned)jx0 >= NB) { wx0 = 0.f; jx0 = 0; }
                if ((unsigned)jx1 >= NB) { wx1 = 0.f; jx1 = 0; }
                if ((unsigned)jy0 >= NB) { wy0 = 0.f; jy0 = 0; }
                if ((unsigned)jy1 >= NB) { wy1 = 0.f; jy1 = 0; }
                if ((unsigned)jz0 >= NB) { wz0 = 0.f; jz0 = 0; }
                if ((unsigned)jz1 >= NB) { wz1 = 0.f; jz1 = 0; }
                float sg = s ? -1.f : 1.f;
                float wzy00 = wz0*wy0*sg, wzy01 = wz0*wy1*sg;
                float wzy10 = wz1*wy0*sg, wzy11 = wz1*wy1*sg;
                int r00 = jz0*SZ + jy0*SY, r01 = jz0*SZ + jy1*SY;
                int r10 = jz1*SZ + jy0*SY, r11 = jz1*SZ + jy1*SY;
                int offs[8] = { r00+jx0, r00+jx1, r01+jx0, r01+jx1,
                                r10+jx0, r10+jx1, r11+jx0, r11+jx1 };
                float wgt[8] = { wzy00*wx0, wzy00*wx1, wzy01*wx0, wzy01*wx1,
                                 wzy10*wx0, wzy10*wx1, wzy11*wx0, wzy11*wx1 };
                #pragma unroll
                for (int j = 0; j < 8; j++) {
                    const __half2* pj = brick2 + offs[j];   // one address per corner
                    float w = wgt[j];
                    #pragma unroll
                    for (int c2 = 0; c2 < NPAIR; c2++) {    // LDS.32 half2, immediate offset
                        float2 v = __half22float2(pj[c2 * PSV]);
                        acc[2*c2]   = fmaf(w, v.x, acc[2*c2]);
                        acc[2*c2+1] = fmaf(w, v.y, acc[2*c2+1]);
                    }
                }
            }
            #pragma unroll
            for (int c = 0; c < C16; c++)
                out[out_base0 + (size_t)c * (FEATS*KTOT) + k] = acc[c];
        }
    } else {
        // mode 1: rare oversized bbox -> direct global gathers (full fp32)
        #pragma unroll
        for (int it = 0; it < 2; it++) {
            int k = k0 + it*THREADS + tid;
            float acc[C16];
            #pragma unroll
            for (int c = 0; c < C16; c++) acc[c] = 0.f;

            #pragma unroll
            for (int s = 0; s < 2; s++) {
                const float* wp = W6 + s*3*KTOT + k;
                float w0 = __ldg(wp);
                float w1 = __ldg(wp + KTOT);
                float w2 = __ldg(wp + 2*KTOT);
                float px = fmaf(ax0, w0, fmaf(ax1, w1, fmaf(ax2, w2, bx)));
                float py = fmaf(ay0, w0, fmaf(ay1, w1, fmaf(ay2, w2, by)));
                float pz = fmaf(az0, w0, fmaf(az1, w1, fmaf(az2, w2, bz)));
                float fx = floorf(px), fy = floorf(py), fz = floorf(pz);
                float tx = px - fx, ty = py - fy, tz = pz - fz;
                int jx0 = (int)fx, jy0 = (int)fy, jz0 = (int)fz;
                int jx1 = jx0 + 1, jy1 = jy0 + 1, jz1 = jz0 + 1;
                float wx0 = 1.f - tx, wx1 = tx;
                float wy0 = 1.f - ty, wy1 = ty;
                float wz0 = 1.f - tz, wz1 = tz;
                if ((unsigned)jx0 >= (unsigned)DIM) { wx0 = 0.f; jx0 = 0; }
                if ((unsigned)jx1 >= (unsigned)DIM) { wx1 = 0.f; jx1 = 0; }
                if ((unsigned)jy0 >= (unsigned)DIM) { wy0 = 0.f; jy0 = 0; }
                if ((unsigned)jy1 >= (unsigned)DIM) { wy1 = 0.f; jy1 = 0; }
                if ((unsigned)jz0 >= (unsigned)DIM) { wz0 = 0.f; jz0 = 0; }
                if ((unsigned)jz1 >= (unsigned)DIM) { wz1 = 0.f; jz1 = 0; }
                float sg = s ? -1.f : 1.f;
                float wzy00 = wz0*wy0*sg, wzy01 = wz0*wy1*sg;
                float wzy10 = wz1*wy0*sg, wzy11 = wz1*wy1*sg;
                int r00 = jz0*HW + jy0*DIM, r01 = jz0*HW + jy1*DIM;
                int r10 = jz1*HW + jy0*DIM, r11 = jz1*HW + jy1*DIM;
                int offs[8] = { r00+jx0, r00+jx1, r01+jx0, r01+jx1,
                                r10+jx0, r10+jx1, r11+jx0, r11+jx1 };
                float wgt[8] = { wzy00*wx0, wzy00*wx1, wzy01*wx0, wzy01*wx1,
                                 wzy10*wx0, wzy10*wx1, wzy11*wx0, wzy11*wx1 };
                #pragma unroll
                for (int j = 0; j < 8; j++) {
                    const float* pj = volb + offs[j];
                    float w = wgt[j];
                    #pragma unroll
                    for (int c = 0; c < C16; c++)
                        acc[c] = fmaf(w, __ldg(pj + (size_t)c * DHW), acc[c]);
                }
            }
            #pragma unroll
            for (int c = 0; c < C16; c++)
                out[out_base0 + (size_t)c * (FEATS*KTOT) + k] = acc[c];
        }
    }
}

extern "C" void kernel_launch(void* const* d_in, const int* in_sizes, int n_in,
                              void* d_out, int out_size)
{
    const float* vol  = (const float*)d_in[0];  // [2,16,96,96,96]
    const float* xyz  = (const float*)d_in[1];  // [2,512,3]
    const float* Amat = (const float*)d_in[2];  // [1024,3,3]
    const float* W6   = (const float*)d_in[3];  // [6,1024]
    float* out = (float*)d_out;                 // [2, 16*512, 1024]

    const int nblocks = 2 * 2 * FEATS;          // 2048
    obelisk_kernel<<<nblocks, THREADS>>>(vol, xyz, Amat, W6, out);
}

// round 10
// speedup vs baseline: 1.6077x; 1.0696x over previous
#include <cuda_runtime.h>
#include <cuda_fp16.h>

#define THREADS 256
#define C16 16
#define DIM 96
#define HW (DIM*DIM)
#define DHW (DIM*DIM*DIM)
#define FEATS 512
#define KTOT 1024
#define KPB 512            // k per block (KSPLIT=2)
#define NB 8               // fixed brick edge
// padded strides in uint2 (8B) units: x=1, y=9, z=77
// 4B-bank analysis and 8B-bank (mod 16) analysis both conflict-free for |delta|<=1
#define SY 9
#define SZ 77
#define PSV (NB*SZ)        // 616 uint2 per channel-quad slab
#define NQUAD 4            // 16 channels = 4 quads (uint2 = 2 x half2)
#define BRICK_E (NQUAD*PSV) // 2464 uint2 = 19.7KB

__global__ void __launch_bounds__(THREADS, 4)
obelisk_kernel(const float* __restrict__ vol,
               const float* __restrict__ xyz,
               const float* __restrict__ Amat,
               const float* __restrict__ W6,
               float* __restrict__ out)
{
    __shared__ uint2 brickq[BRICK_E];   // 19.7KB static
    __shared__ float sP[12];
    __shared__ int   sBox[4];           // xlo,ylo,zlo,mode
    __shared__ float sRed[6*8];

    const int tid  = threadIdx.x;
    const int lane = tid & 31;
    const int wid  = tid >> 5;
    const int blk  = blockIdx.x;
    const int pt   = blk >> 1;
    const int kh   = blk & 1;
    const int b    = pt >> 9;
    const int f    = pt & (FEATS - 1);
    const int k0   = kh * KPB;

    if (tid == 0) {
        float x0 = xyz[pt*3+0], x1 = xyz[pt*3+1], x2 = xyz[pt*3+2];
        sP[0] = (x0 + 1.f) * 48.f - 0.5f;
        sP[1] = (x1 + 1.f) * 48.f - 0.5f;
        sP[2] = (x2 + 1.f) * 48.f - 0.5f;
        const float* Ar = Amat + pt * 9;
        sP[3] = 48.f*Ar[6]; sP[4]  = 48.f*Ar[7]; sP[5]  = 48.f*Ar[8];  // x row
        sP[6] = 48.f*Ar[3]; sP[7]  = 48.f*Ar[4]; sP[8]  = 48.f*Ar[5];  // y row
        sP[9] = 48.f*Ar[0]; sP[10] = 48.f*Ar[1]; sP[11] = 48.f*Ar[2];  // z row
    }
    __syncthreads();

    const float bx = sP[0], by = sP[1], bz = sP[2];
    const float ax0 = sP[3], ax1 = sP[4],  ax2 = sP[5];
    const float ay0 = sP[6], ay1 = sP[7],  ay2 = sP[8];
    const float az0 = sP[9], az1 = sP[10], az2 = sP[11];

    // ---------------- Pass 1: bbox of all sample coords (same FP exprs as pass 2)
    float mnx = 1e30f, mxx = -1e30f;
    float mny = 1e30f, mxy = -1e30f;
    float mnz = 1e30f, mxz = -1e30f;
    #pragma unroll
    for (int it = 0; it < 2; it++) {
        int k = k0 + it*THREADS + tid;
        #pragma unroll
        for (int s = 0; s < 2; s++) {
            const float* wp = W6 + s*3*KTOT + k;
            float w0 = __ldg(wp);
            float w1 = __ldg(wp + KTOT);
            float w2 = __ldg(wp + 2*KTOT);
            float px = fmaf(ax0, w0, fmaf(ax1, w1, fmaf(ax2, w2, bx)));
            float py = fmaf(ay0, w0, fmaf(ay1, w1, fmaf(ay2, w2, by)));
            float pz = fmaf(az0, w0, fmaf(az1, w1, fmaf(az2, w2, bz)));
            mnx = fminf(mnx, px); mxx = fmaxf(mxx, px);
            mny = fminf(mny, py); mxy = fmaxf(mxy, py);
            mnz = fminf(mnz, pz); mxz = fmaxf(mxz, pz);
        }
    }
    float r0 = mnx, r1 = -mxx, r2 = mny, r3 = -mxy, r4 = mnz, r5 = -mxz;
    #pragma unroll
    for (int o = 16; o > 0; o >>= 1) {
        r0 = fminf(r0, __shfl_xor_sync(0xffffffffu, r0, o));
        r1 = fminf(r1, __shfl_xor_sync(0xffffffffu, r1, o));
        r2 = fminf(r2, __shfl_xor_sync(0xffffffffu, r2, o));
        r3 = fminf(r3, __shfl_xor_sync(0xffffffffu, r3, o));
        r4 = fminf(r4, __shfl_xor_sync(0xffffffffu, r4, o));
        r5 = fminf(r5, __shfl_xor_sync(0xffffffffu, r5, o));
    }
    if (lane == 0) {
        sRed[0*8+wid] = r0; sRed[1*8+wid] = r1; sRed[2*8+wid] = r2;
        sRed[3*8+wid] = r3; sRed[4*8+wid] = r4; sRed[5*8+wid] = r5;
    }
    __syncthreads();
    if (tid == 0) {
        float m0 = sRed[0], m1 = sRed[8], m2 = sRed[16], m3 = sRed[24], m4 = sRed[32], m5 = sRed[40];
        #pragma unroll
        for (int i = 1; i < 8; i++) {
            m0 = fminf(m0, sRed[0*8+i]); m1 = fminf(m1, sRed[1*8+i]);
            m2 = fminf(m2, sRed[2*8+i]); m3 = fminf(m3, sRed[3*8+i]);
            m4 = fminf(m4, sRed[4*8+i]); m5 = fminf(m5, sRed[5*8+i]);
        }
        float MX = -m1, MY = -m3, MZ = -m5;
        int xlo = max(0, (int)floorf(m0));
        int xhi = min(DIM - 1, (int)floorf(MX) + 1);
        int ylo = max(0, (int)floorf(m2));
        int yhi = min(DIM - 1, (int)floorf(MY) + 1);
        int zlo = max(0, (int)floorf(m4));
        int zhi = min(DIM - 1, (int)floorf(MZ) + 1);
        int nx = xhi - xlo + 1, ny = yhi - ylo + 1, nz = zhi - zlo + 1;
        int mode;
        if (nx <= 0 || ny <= 0 || nz <= 0) mode = 2;                   // fully outside
        else if (nx <= NB && ny <= NB && nz <= NB) mode = 0;           // fixed 8^3 brick
        else mode = 1;                                                 // global fallback
        // anchor clamp: brick [lo, lo+7] always inside volume
        sBox[0] = min(xlo, DIM - NB);
        sBox[1] = min(ylo, DIM - NB);
        sBox[2] = min(zlo, DIM - NB);
        sBox[3] = mode;
    }
    __syncthreads();

    const int xlo = sBox[0], ylo = sBox[1], zlo = sBox[2];
    const int mode = sBox[3];

    const size_t out_base0 = (((size_t)b * C16) * FEATS + f) * KTOT;

    if (mode == 2) {
        #pragma unroll
        for (int it = 0; it < 2; it++) {
            int k = k0 + it*THREADS + tid;
            #pragma unroll
            for (int c = 0; c < C16; c++)
                out[out_base0 + (size_t)c * (FEATS*KTOT) + k] = 0.f;
        }
        return;
    }

    const float* volb = vol + (size_t)b * C16 * DHW;

    // --- Brick load: 8x8x8 voxels x 4 channel-quads, fp16x4 (uint2) padded layout ---
    if (mode == 0) {
        const float* src = volb + (size_t)zlo * HW + ylo * DIM + xlo;
        #pragma unroll
        for (int t = 0; t < (NQUAD*NB*NB*NB) / THREADS; t++) {   // 8 iters
            int m = t * THREADS + tid;
            int x  = m & 7;
            int y  = (m >> 3) & 7;
            int z  = (m >> 6) & 7;
            int c4 = m >> 9;
            const float* s0 = src + (size_t)(4*c4) * DHW + z * HW + y * DIM + x;
            float v0 = __ldg(s0);
            float v1 = __ldg(s0 + DHW);
            float v2 = __ldg(s0 + 2*DHW);
            float v3 = __ldg(s0 + 3*DHW);
            __half2 h0 = __floats2half2_rn(v0, v1);
            __half2 h1 = __floats2half2_rn(v2, v3);
            uint2 q;
            q.x = *reinterpret_cast<unsigned int*>(&h0);
            q.y = *reinterpret_cast<unsigned int*>(&h1);
            brickq[c4 * PSV + z * SZ + y * SY + x] = q;
        }
    }
    __syncthreads();

    // ---------------- Main sampling loop ----------------
    if (mode == 0) {
        #pragma unroll
        for (int it = 0; it < 2; it++) {
            int k = k0 + it*THREADS + tid;
            // 16 fp32 accumulators held as 8 packed f32x2 (64-bit) regs
            unsigned long long acc64[8];
            #pragma unroll
            for (int p = 0; p < 8; p++) acc64[p] = 0ull;

            // load all 6 offset weights up front (batch both LDG latencies)
            float w0a = __ldg(W6 + k);
            float w1a = __ldg(W6 + KTOT + k);
            float w2a = __ldg(W6 + 2*KTOT + k);
            float w0b = __ldg(W6 + 3*KTOT + k);
            float w1b = __ldg(W6 + 4*KTOT + k);
            float w2b = __ldg(W6 + 5*KTOT + k);

            #pragma unroll
            for (int s = 0; s < 2; s++) {
                float w0 = s ? w0b : w0a;
                float w1 = s ? w1b : w1a;
                float w2 = s ? w2b : w2a;
                float px = fmaf(ax0, w0, fmaf(ax1, w1, fmaf(ax2, w2, bx)));
                float py = fmaf(ay0, w0, fmaf(ay1, w1, fmaf(ay2, w2, by)));
                float pz = fmaf(az0, w0, fmaf(az1, w1, fmaf(az2, w2, bz)));
                float fx = floorf(px), fy = floorf(py), fz = floorf(pz);
                float tx = px - fx, ty = py - fy, tz = pz - fz;
                int jx0 = (int)fx - xlo, jy0 = (int)fy - ylo, jz0 = (int)fz - zlo;
                int jx1 = jx0 + 1, jy1 = jy0 + 1, jz1 = jz0 + 1;
                float wx0 = 1.f - tx, wx1 = tx;
                float wy0 = 1.f - ty, wy1 = ty;
                float wz0 = 1.f - tz, wz1 = tz;
                // out-of-brick == out-of-volume: zero weight + clamp index
                if ((unsigned)jx0 >= NB) { wx0 = 0.f; jx0 = 0; }
                if ((unsigned)jx1 >= NB) { wx1 = 0.f; jx1 = 0; }
                if ((unsigned)jy0 >= NB) { wy0 = 0.f; jy0 = 0; }
                if ((unsigned)jy1 >= NB) { wy1 = 0.f; jy1 = 0; }
                if ((unsigned)jz0 >= NB) { wz0 = 0.f; jz0 = 0; }
                if ((unsigned)jz1 >= NB) { wz1 = 0.f; jz1 = 0; }
                float sg = s ? -1.f : 1.f;
                float wzy00 = wz0*wy0*sg, wzy01 = wz0*wy1*sg;
                float wzy10 = wz1*wy0*sg, wzy11 = wz1*wy1*sg;
                int r00 = jz0*SZ + jy0*SY, r01 = jz0*SZ + jy1*SY;
                int r10 = jz1*SZ + jy0*SY, r11 = jz1*SZ + jy1*SY;
                int offs[8] = { r00+jx0, r00+jx1, r01+jx0, r01+jx1,
                                r10+jx0, r10+jx1, r11+jx0, r11+jx1 };
                float wgt[8] = { wzy00*wx0, wzy00*wx1, wzy01*wx0, wzy01*wx1,
                                 wzy10*wx0, wzy10*wx1, wzy11*wx0, wzy11*wx1 };
                #pragma unroll
                for (int j = 0; j < 8; j++) {
                    const uint2* pj = brickq + offs[j];   // one address per corner
                    unsigned long long w2pk;
                    unsigned int wbits = __float_as_uint(wgt[j]);
                    asm("mov.b64 %0, {%1, %1};" : "=l"(w2pk) : "r"(wbits));
                    #pragma unroll
                    for (int c4 = 0; c4 < NQUAD; c4++) {  // LDS.64, immediate c4*PSV*8
                        uint2 q = pj[c4 * PSV];
                        __half2 h0 = *reinterpret_cast<__half2*>(&q.x);
                        __half2 h1 = *reinterpret_cast<__half2*>(&q.y);
                        float2 f0 = __half22float2(h0);
                        float2 f1 = __half22float2(h1);
                        unsigned long long v0, v1;
                        asm("mov.b64 %0, {%1, %2};" : "=l"(v0) : "f"(f0.x), "f"(f0.y));
                        asm("mov.b64 %0, {%1, %2};" : "=l"(v1) : "f"(f1.x), "f"(f1.y));
                        asm("fma.rn.f32x2 %0, %1, %2, %0;" : "+l"(acc64[2*c4])   : "l"(v0), "l"(w2pk));
                        asm("fma.rn.f32x2 %0, %1, %2, %0;" : "+l"(acc64[2*c4+1]) : "l"(v1), "l"(w2pk));
                    }
                }
            }
            #pragma unroll
            for (int p = 0; p < 8; p++) {
                float lo, hi;
                asm("mov.b64 {%0, %1}, %2;" : "=f"(lo), "=f"(hi) : "l"(acc64[p]));
                out[out_base0 + (size_t)(2*p)   * (FEATS*KTOT) + k] = lo;
                out[out_base0 + (size_t)(2*p+1) * (FEATS*KTOT) + k] = hi;
            }
        }
    } else {
        // mode 1: rare oversized bbox -> direct global gathers (full fp32)
        #pragma unroll
        for (int it = 0; it < 2; it++) {
            int k = k0 + it*THREADS + tid;
            float acc[C16];
            #pragma unroll
            for (int c = 0; c < C16; c++) acc[c] = 0.f;

            #pragma unroll
            for (int s = 0; s < 2; s++) {
                const float* wp = W6 + s*3*KTOT + k;
                float w0 = __ldg(wp);
                float w1 = __ldg(wp + KTOT);
                float w2 = __ldg(wp + 2*KTOT);
                float px = fmaf(ax0, w0, fmaf(ax1, w1, fmaf(ax2, w2, bx)));
                float py = fmaf(ay0, w0, fmaf(ay1, w1, fmaf(ay2, w2, by)));
                float pz = fmaf(az0, w0, fmaf(az1, w1, fmaf(az2, w2, bz)));
                float fx = floorf(px), fy = floorf(py), fz = floorf(pz);
                float tx = px - fx, ty = py - fy, tz = pz - fz;
                int jx0 = (int)fx, jy0 = (int)fy, jz0 = (int)fz;
                int jx1 = jx0 + 1, jy1 = jy0 + 1, jz1 = jz0 + 1;
                float wx0 = 1.f - tx, wx1 = tx;
                float wy0 = 1.f - ty, wy1 = ty;
                float wz0 = 1.f - tz, wz1 = tz;
                if ((unsigned)jx0 >= (unsigned)DIM) { wx0 = 0.f; jx0 = 0; }
                if ((unsigned)jx1 >= (unsigned)DIM) { wx1 = 0.f; jx1 = 0; }
                if ((unsigned)jy0 >= (unsigned)DIM) { wy0 = 0.f; jy0 = 0; }
                if ((unsigned)jy1 >= (unsigned)DIM) { wy1 = 0.f; jy1 = 0; }
                if ((unsigned)jz0 >= (unsigned)DIM) { wz0 = 0.f; jz0 = 0; }
                if ((unsigned)jz1 >= (unsigned)DIM) { wz1 = 0.f; jz1 = 0; }
                float sg = s ? -1.f : 1.f;
                float wzy00 = wz0*wy0*sg, wzy01 = wz0*wy1*sg;
                float wzy10 = wz1*wy0*sg, wzy11 = wz1*wy1*sg;
                int r00 = jz0*HW + jy0*DIM, r01 = jz0*HW + jy1*DIM;
                int r10 = jz1*HW + jy0*DIM, r11 = jz1*HW + jy1*DIM;
                int offs[8] = { r00+jx0, r00+jx1, r01+jx0, r01+jx1,
                                r10+jx0, r10+jx1, r11+jx0, r11+jx1 };
                float wgt[8] = { wzy00*wx0, wzy00*wx1, wzy01*wx0, wzy01*wx1,
                                 wzy10*wx0, wzy10*wx1, wzy11*wx0, wzy11*wx1 };
                #pragma unroll
                for (int j = 0; j < 8; j++) {
                    const float* pj = volb + offs[j];
                    float w = wgt[j];
                    #pragma unroll
                    for (int c = 0; c < C16; c++)
                        acc[c] = fmaf(w, __ldg(pj + (size_t)c * DHW), acc[c]);
                }
            }
            #pragma unroll
            for (int c = 0; c < C16; c++)
                out[out_base0 + (size_t)c * (FEATS*KTOT) + k] = acc[c];
        }
    }
}

extern "C" void kernel_launch(void* const* d_in, const int* in_sizes, int n_in,
                              void* d_out, int out_size)
{
    const float* vol  = (const float*)d_in[0];  // [2,16,96,96,96]
    const float* xyz  = (const float*)d_in[1];  // [2,512,3]
    const float* Amat = (const float*)d_in[2];  // [1024,3,3]
    const float* W6   = (const float*)d_in[3];  // [6,1024]
    float* out = (float*)d_out;                 // [2, 16*512, 1024]

    const int nblocks = 2 * 2 * FEATS;          // 2048
    obelisk_kernel<<<nblocks, THREADS>>>(vol, xyz, Amat, W6, out);
}

// round 11
// speedup vs baseline: 1.6212x; 1.0084x over previous
#include <cuda_runtime.h>
#include <cuda_fp16.h>

#define THREADS 256
#define C16 16
#define DIM 96
#define HW (DIM*DIM)
#define DHW (DIM*DIM*DIM)
#define FEATS 512
#define KTOT 1024
#define KPB 512            // k per block (KSPLIT=2)
#define NB 8               // fixed brick edge
// padded strides in uint4 (16B) units: x=1, y=10, z=84
// bank-group(16B) = (84*jz + 10*jy + jx) mod 8 -> nonzero for every |delta|<=1 offset
// (84*dz + 10*dy + dx) mod 8 over dz,dy,dx in {-1,0,1}: {4dz+2dy+dx} -> never 0
#define SY 10
#define SZ 84
#define PSV (NB*SZ)        // 672 uint4 per channel-octet slab
#define NOCT 2             // 16 channels = 2 octets (uint4 = 4 x half2)
#define BRICK_E (NOCT*PSV) // 1344 uint4 = 21KB

__global__ void __launch_bounds__(THREADS, 3)
obelisk_kernel(const float* __restrict__ vol,
               const float* __restrict__ xyz,
               const float* __restrict__ Amat,
               const float* __restrict__ W6,
               float* __restrict__ out)
{
    __shared__ uint4 brickq[BRICK_E];   // 21KB static
    __shared__ float sP[12];
    __shared__ int   sBox[4];           // xlo,ylo,zlo,mode
    __shared__ float sRed[6*8];

    const int tid  = threadIdx.x;
    const int lane = tid & 31;
    const int wid  = tid >> 5;
    const int blk  = blockIdx.x;
    const int pt   = blk >> 1;
    const int kh   = blk & 1;
    const int b    = pt >> 9;
    const int f    = pt & (FEATS - 1);
    const int k0   = kh * KPB;

    if (tid == 0) {
        float x0 = xyz[pt*3+0], x1 = xyz[pt*3+1], x2 = xyz[pt*3+2];
        sP[0] = (x0 + 1.f) * 48.f - 0.5f;
        sP[1] = (x1 + 1.f) * 48.f - 0.5f;
        sP[2] = (x2 + 1.f) * 48.f - 0.5f;
        const float* Ar = Amat + pt * 9;
        sP[3] = 48.f*Ar[6]; sP[4]  = 48.f*Ar[7]; sP[5]  = 48.f*Ar[8];  // x row
        sP[6] = 48.f*Ar[3]; sP[7]  = 48.f*Ar[4]; sP[8]  = 48.f*Ar[5];  // y row
        sP[9] = 48.f*Ar[0]; sP[10] = 48.f*Ar[1]; sP[11] = 48.f*Ar[2];  // z row
    }
    __syncthreads();

    const float bx = sP[0], by = sP[1], bz = sP[2];
    const float ax0 = sP[3], ax1 = sP[4],  ax2 = sP[5];
    const float ay0 = sP[6], ay1 = sP[7],  ay2 = sP[8];
    const float az0 = sP[9], az1 = sP[10], az2 = sP[11];

    // ---------------- Pass 1: bbox of all sample coords (same FP exprs as pass 2)
    float mnx = 1e30f, mxx = -1e30f;
    float mny = 1e30f, mxy = -1e30f;
    float mnz = 1e30f, mxz = -1e30f;
    #pragma unroll
    for (int it = 0; it < 2; it++) {
        int k = k0 + it*THREADS + tid;
        #pragma unroll
        for (int s = 0; s < 2; s++) {
            const float* wp = W6 + s*3*KTOT + k;
            float w0 = __ldg(wp);
            float w1 = __ldg(wp + KTOT);
            float w2 = __ldg(wp + 2*KTOT);
            float px = fmaf(ax0, w0, fmaf(ax1, w1, fmaf(ax2, w2, bx)));
            float py = fmaf(ay0, w0, fmaf(ay1, w1, fmaf(ay2, w2, by)));
            float pz = fmaf(az0, w0, fmaf(az1, w1, fmaf(az2, w2, bz)));
            mnx = fminf(mnx, px); mxx = fmaxf(mxx, px);
            mny = fminf(mny, py); mxy = fmaxf(mxy, py);
            mnz = fminf(mnz, pz); mxz = fmaxf(mxz, pz);
        }
    }
    float r0 = mnx, r1 = -mxx, r2 = mny, r3 = -mxy, r4 = mnz, r5 = -mxz;
    #pragma unroll
    for (int o = 16; o > 0; o >>= 1) {
        r0 = fminf(r0, __shfl_xor_sync(0xffffffffu, r0, o));
        r1 = fminf(r1, __shfl_xor_sync(0xffffffffu, r1, o));
        r2 = fminf(r2, __shfl_xor_sync(0xffffffffu, r2, o));
        r3 = fminf(r3, __shfl_xor_sync(0xffffffffu, r3, o));
        r4 = fminf(r4, __shfl_xor_sync(0xffffffffu, r4, o));
        r5 = fminf(r5, __shfl_xor_sync(0xffffffffu, r5, o));
    }
    if (lane == 0) {
        sRed[0*8+wid] = r0; sRed[1*8+wid] = r1; sRed[2*8+wid] = r2;
        sRed[3*8+wid] = r3; sRed[4*8+wid] = r4; sRed[5*8+wid] = r5;
    }
    __syncthreads();
    if (tid == 0) {
        float m0 = sRed[0], m1 = sRed[8], m2 = sRed[16], m3 = sRed[24], m4 = sRed[32], m5 = sRed[40];
        #pragma unroll
        for (int i = 1; i < 8; i++) {
            m0 = fminf(m0, sRed[0*8+i]); m1 = fminf(m1, sRed[1*8+i]);
            m2 = fminf(m2, sRed[2*8+i]); m3 = fminf(m3, sRed[3*8+i]);
            m4 = fminf(m4, sRed[4*8+i]); m5 = fminf(m5, sRed[5*8+i]);
        }
        float MX = -m1, MY = -m3, MZ = -m5;
        int xlo = max(0, (int)floorf(m0));
        int xhi = min(DIM - 1, (int)floorf(MX) + 1);
        int ylo = max(0, (int)floorf(m2));
        int yhi = min(DIM - 1, (int)floorf(MY) + 1);
        int zlo = max(0, (int)floorf(m4));
        int zhi = min(DIM - 1, (int)floorf(MZ) + 1);
        int nx = xhi - xlo + 1, ny = yhi - ylo + 1, nz = zhi - zlo + 1;
        int mode;
        if (nx <= 0 || ny <= 0 || nz <= 0) mode = 2;                   // fully outside
        else if (nx <= NB && ny <= NB && nz <= NB) mode = 0;           // fixed 8^3 brick
        else mode = 1;                                                 // global fallback
        // anchor clamp: brick [lo, lo+7] always inside volume
        sBox[0] = min(xlo, DIM - NB);
        sBox[1] = min(ylo, DIM - NB);
        sBox[2] = min(zlo, DIM - NB);
        sBox[3] = mode;
    }
    __syncthreads();

    const int xlo = sBox[0], ylo = sBox[1], zlo = sBox[2];
    const int mode = sBox[3];

    const size_t out_base0 = (((size_t)b * C16) * FEATS + f) * KTOT;

    if (mode == 2) {
        #pragma unroll
        for (int it = 0; it < 2; it++) {
            int k = k0 + it*THREADS + tid;
            #pragma unroll
            for (int c = 0; c < C16; c++)
                out[out_base0 + (size_t)c * (FEATS*KTOT) + k] = 0.f;
        }
        return;
    }

    const float* volb = vol + (size_t)b * C16 * DHW;

    // --- Brick load: 8x8x8 voxels x 2 channel-octets, fp16x8 (uint4) padded layout ---
    if (mode == 0) {
        const float* src = volb + (size_t)zlo * HW + ylo * DIM + xlo;
        #pragma unroll
        for (int t = 0; t < (NOCT*NB*NB*NB) / THREADS; t++) {   // 4 iters
            int m = t * THREADS + tid;
            int x  = m & 7;
            int y  = (m >> 3) & 7;
            int z  = (m >> 6) & 7;
            int c8 = m >> 9;
            const float* s0 = src + (size_t)(8*c8) * DHW + z * HW + y * DIM + x;
            __half2 h0 = __floats2half2_rn(__ldg(s0),         __ldg(s0 + DHW));
            __half2 h1 = __floats2half2_rn(__ldg(s0 + 2*DHW), __ldg(s0 + 3*DHW));
            __half2 h2 = __floats2half2_rn(__ldg(s0 + 4*DHW), __ldg(s0 + 5*DHW));
            __half2 h3 = __floats2half2_rn(__ldg(s0 + 6*DHW), __ldg(s0 + 7*DHW));
            uint4 q;
            q.x = *reinterpret_cast<unsigned int*>(&h0);
            q.y = *reinterpret_cast<unsigned int*>(&h1);
            q.z = *reinterpret_cast<unsigned int*>(&h2);
            q.w = *reinterpret_cast<unsigned int*>(&h3);
            brickq[c8 * PSV + z * SZ + y * SY + x] = q;
        }
    }
    __syncthreads();

    // ---------------- Main sampling loop ----------------
    if (mode == 0) {
        #pragma unroll
        for (int it = 0; it < 2; it++) {
            int k = k0 + it*THREADS + tid;
            // 16 fp32 accumulators held as 8 packed f32x2 (64-bit) regs
            unsigned long long acc64[8];
            #pragma unroll
            for (int p = 0; p < 8; p++) acc64[p] = 0ull;

            // load all 6 offset weights up front (batch both LDG latencies)
            float w0a = __ldg(W6 + k);
            float w1a = __ldg(W6 + KTOT + k);
            float w2a = __ldg(W6 + 2*KTOT + k);
            float w0b = __ldg(W6 + 3*KTOT + k);
            float w1b = __ldg(W6 + 4*KTOT + k);
            float w2b = __ldg(W6 + 5*KTOT + k);

            #pragma unroll
            for (int s = 0; s < 2; s++) {
                float w0 = s ? w0b : w0a;
                float w1 = s ? w1b : w1a;
                float w2 = s ? w2b : w2a;
                float px = fmaf(ax0, w0, fmaf(ax1, w1, fmaf(ax2, w2, bx)));
                float py = fmaf(ay0, w0, fmaf(ay1, w1, fmaf(ay2, w2, by)));
                float pz = fmaf(az0, w0, fmaf(az1, w1, fmaf(az2, w2, bz)));
                float fx = floorf(px), fy = floorf(py), fz = floorf(pz);
                float tx = px - fx, ty = py - fy, tz = pz - fz;
                int jx0 = (int)fx - xlo, jy0 = (int)fy - ylo, jz0 = (int)fz - zlo;
                int jx1 = jx0 + 1, jy1 = jy0 + 1, jz1 = jz0 + 1;
                float wx0 = 1.f - tx, wx1 = tx;
                float wy0 = 1.f - ty, wy1 = ty;
                float wz0 = 1.f - tz, wz1 = tz;
                // out-of-brick == out-of-volume: zero weight + clamp index
                if ((unsigned)jx0 >= NB) { wx0 = 0.f; jx0 = 0; }
                if ((unsigned)jx1 >= NB) { wx1 = 0.f; jx1 = 0; }
                if ((unsigned)jy0 >= NB) { wy0 = 0.f; jy0 = 0; }
                if ((unsigned)jy1 >= NB) { wy1 = 0.f; jy1 = 0; }
                if ((unsigned)jz0 >= NB) { wz0 = 0.f; jz0 = 0; }
                if ((unsigned)jz1 >= NB) { wz1 = 0.f; jz1 = 0; }
                float sg = s ? -1.f : 1.f;
                float wzy00 = wz0*wy0*sg, wzy01 = wz0*wy1*sg;
                float wzy10 = wz1*wy0*sg, wzy11 = wz1*wy1*sg;
                int r00 = jz0*SZ + jy0*SY, r01 = jz0*SZ + jy1*SY;
                int r10 = jz1*SZ + jy0*SY, r11 = jz1*SZ + jy1*SY;
                int offs[8] = { r00+jx0, r00+jx1, r01+jx0, r01+jx1,
                                r10+jx0, r10+jx1, r11+jx0, r11+jx1 };
                float wgt[8] = { wzy00*wx0, wzy00*wx1, wzy01*wx0, wzy01*wx1,
                                 wzy10*wx0, wzy10*wx1, wzy11*wx0, wzy11*wx1 };
                #pragma unroll
                for (int j = 0; j < 8; j++) {
                    const uint4* pj = brickq + offs[j];   // one address per corner
                    unsigned long long w2pk;
                    unsigned int wbits = __float_as_uint(wgt[j]);
                    asm("mov.b64 %0, {%1, %1};" : "=l"(w2pk) : "r"(wbits));
                    #pragma unroll
                    for (int c8 = 0; c8 < NOCT; c8++) {   // LDS.128, immediate c8*PSV*16
                        uint4 q = pj[c8 * PSV];
                        __half2 h0 = *reinterpret_cast<__half2*>(&q.x);
                        __half2 h1 = *reinterpret_cast<__half2*>(&q.y);
                        __half2 h2 = *reinterpret_cast<__half2*>(&q.z);
                        __half2 h3 = *reinterpret_cast<__half2*>(&q.w);
                        float2 f0 = __half22float2(h0);
                        float2 f1 = __half22float2(h1);
                        float2 f2 = __half22float2(h2);
                        float2 f3 = __half22float2(h3);
                        unsigned long long v0, v1, v2, v3;
                        asm("mov.b64 %0, {%1, %2};" : "=l"(v0) : "f"(f0.x), "f"(f0.y));
                        asm("mov.b64 %0, {%1, %2};" : "=l"(v1) : "f"(f1.x), "f"(f1.y));
                        asm("mov.b64 %0, {%1, %2};" : "=l"(v2) : "f"(f2.x), "f"(f2.y));
                        asm("mov.b64 %0, {%1, %2};" : "=l"(v3) : "f"(f3.x), "f"(f3.y));
                        asm("fma.rn.f32x2 %0, %1, %2, %0;" : "+l"(acc64[4*c8])   : "l"(v0), "l"(w2pk));
                        asm("fma.rn.f32x2 %0, %1, %2, %0;" : "+l"(acc64[4*c8+1]) : "l"(v1), "l"(w2pk));
                        asm("fma.rn.f32x2 %0, %1, %2, %0;" : "+l"(acc64[4*c8+2]) : "l"(v2), "l"(w2pk));
                        asm("fma.rn.f32x2 %0, %1, %2, %0;" : "+l"(acc64[4*c8+3]) : "l"(v3), "l"(w2pk));
                    }
                }
            }
            #pragma unroll
            for (int p = 0; p < 8; p++) {
                float lo, hi;
                asm("mov.b64 {%0, %1}, %2;" : "=f"(lo), "=f"(hi) : "l"(acc64[p]));
                out[out_base0 + (size_t)(2*p)   * (FEATS*KTOT) + k] = lo;
                out[out_base0 + (size_t)(2*p+1) * (FEATS*KTOT) + k] = hi;
            }
        }
    } else {
        // mode 1: rare oversized bbox -> direct global gathers (full fp32)
        #pragma unroll
        for (int it = 0; it < 2; it++) {
            int k = k0 + it*THREADS + tid;
            float acc[C16];
            #pragma unroll
            for (int c = 0; c < C16; c++) acc[c] = 0.f;

            #pragma unroll
            for (int s = 0; s < 2; s++) {
                const float* wp = W6 + s*3*KTOT + k;
                float w0 = __ldg(wp);
                float w1 = __ldg(wp + KTOT);
                float w2 = __ldg(wp + 2*KTOT);
                float px = fmaf(ax0, w0, fmaf(ax1, w1, fmaf(ax2, w2, bx)));
                float py = fmaf(ay0, w0, fmaf(ay1, w1, fmaf(ay2, w2, by)));
                float pz = fmaf(az0, w0, fmaf(az1, w1, fmaf(az2, w2, bz)));
                float fx = floorf(px), fy = floorf(py), fz = floorf(pz);
                float tx = px - fx, ty = py - fy, tz = pz - fz;
                int jx0 = (int)fx, jy0 = (int)fy, jz0 = (int)fz;
                int jx1 = jx0 + 1, jy1 = jy0 + 1, jz1 = jz0 + 1;
                float wx0 = 1.f - tx, wx1 = tx;
                float wy0 = 1.f - ty, wy1 = ty;
                float wz0 = 1.f - tz, wz1 = tz;
                if ((unsigned)jx0 >= (unsigned)DIM) { wx0 = 0.f; jx0 = 0; }
                if ((unsigned)jx1 >= (unsigned)DIM) { wx1 = 0.f; jx1 = 0; }
                if ((unsigned)jy0 >= (unsigned)DIM) { wy0 = 0.f; jy0 = 0; }
                if ((unsigned)jy1 >= (unsigned)DIM) { wy1 = 0.f; jy1 = 0; }
                if ((unsigned)jz0 >= (unsigned)DIM) { wz0 = 0.f; jz0 = 0; }
                if ((unsigned)jz1 >= (unsigned)DIM) { wz1 = 0.f; jz1 = 0; }
                float sg = s ? -1.f : 1.f;
                float wzy00 = wz0*wy0*sg, wzy01 = wz0*wy1*sg;
                float wzy10 = wz1*wy0*sg, wzy11 = wz1*wy1*sg;
                int r00 = jz0*HW + jy0*DIM, r01 = jz0*HW + jy1*DIM;
                int r10 = jz1*HW + jy0*DIM, r11 = jz1*HW + jy1*DIM;
                int offs[8] = { r00+jx0, r00+jx1, r01+jx0, r01+jx1,
                                r10+jx0, r10+jx1, r11+jx0, r11+jx1 };
                float wgt[8] = { wzy00*wx0, wzy00*wx1, wzy01*wx0, wzy01*wx1,
                                 wzy10*wx0, wzy10*wx1, wzy11*wx0, wzy11*wx1 };
                #pragma unroll
                for (int j = 0; j < 8; j++) {
                    const float* pj = volb + offs[j];
                    float w = wgt[j];
                    #pragma unroll
                    for (int c = 0; c < C16; c++)
                        acc[c] = fmaf(w, __ldg(pj + (size_t)c * DHW), acc[c]);
                }
            }
            #pragma unroll
            for (int c = 0; c < C16; c++)
                out[out_base0 + (size_t)c * (FEATS*KTOT) + k] = acc[c];
        }
    }
}

extern "C" void kernel_launch(void* const* d_in, const int* in_sizes, int n_in,
                              void* d_out, int out_size)
{
    const float* vol  = (const float*)d_in[0];  // [2,16,96,96,96]
    const float* xyz  = (const float*)d_in[1];  // [2,512,3]
    const float* Amat = (const float*)d_in[2];  // [1024,3,3]
    const float* W6   = (const float*)d_in[3];  // [6,1024]
    float* out = (float*)d_out;                 // [2, 16*512, 1024]

    const int nblocks = 2 * 2 * FEATS;          // 2048
    obelisk_kernel<<<nblocks, THREADS>>>(vol, xyz, Amat, W6, out);
}